// round 15
// baseline (speedup 1.0000x reference)
#include <cuda_runtime.h>

#define BATCH 256
#define TSTEPS 4096
#define D 64
#define H 192
#define NCLS 10
#define BETA 0.9f
#define KW 8
#define RING 16
#define NWIN (TSTEPS / KW)

typedef unsigned long long ull;

__device__ __forceinline__ ull pack2(float x, float y) {
    ull v; asm("mov.b64 %0, {%1, %2};" : "=l"(v) : "f"(x), "f"(y)); return v;
}
__device__ __forceinline__ void unpack2(ull v, float& x, float& y) {
    asm("mov.b64 {%0, %1}, %2;" : "=f"(x), "=f"(y) : "l"(v));
}
__device__ __forceinline__ void ffma2(ull& d, ull a, ull b) {
    asm("fma.rn.f32x2 %0, %1, %2, %0;" : "+l"(d) : "l"(a), "l"(b));
}

// LIF update for 2 neurons; op order identical to the proven-exact R4/R5 form.
// Internal locals use reserved _l* names (R6 shadowing bug guard).
#define LIF_STEP(ACC, TIDX)                                                    \
    {                                                                          \
        float _la, _lb; unpack2((ACC), _la, _lb);                              \
        float _cur0 = __fadd_rn(_la, eb0);                                     \
        float _cur1 = __fadd_rn(_lb, eb1);                                     \
        mem0 = __fmaf_rn(BETA, mem0, _cur0);                                   \
        mem1 = __fmaf_rn(BETA, mem1, _cur1);                                   \
        float _s0 = (__fadd_rn(mem0, -1.0f) > 0.f) ? 1.f : 0.f;                \
        float _s1 = (__fadd_rn(mem1, -1.0f) > 0.f) ? 1.f : 0.f;                \
        rate0 = __fadd_rn(rate0, _s0);                                         \
        rate1 = __fadd_rn(rate1, _s1);                                         \
        *reinterpret_cast<float2*>(spkc + (size_t)(TIDX) * H) =                \
            make_float2(_s0, _s1);                                             \
        mem0 = __fmul_rn(mem0, __fadd_rn(1.0f, -_s0));                         \
        mem1 = __fmul_rn(mem1, __fadd_rn(1.0f, -_s1));                         \
    }

// Consumer pass: 4 consecutive LIF steps S..S+3 (states s_{S+1}..s_{S+4}).
// 4 independent sequential-k chains interleaved; per-chain k-order preserved.
#define CONS_PASS(S)                                                           \
    {                                                                          \
        const ulonglong2* p0 = (const ulonglong2*)sd[((S) + 1) & (RING - 1)];  \
        const ulonglong2* p1 = (const ulonglong2*)sd[((S) + 2) & (RING - 1)];  \
        const ulonglong2* p2 = (const ulonglong2*)sd[((S) + 3) & (RING - 1)];  \
        const ulonglong2* p3 = (const ulonglong2*)sd[((S) + 4) & (RING - 1)];  \
        ull acc0 = 0, acc1 = 0, acc2 = 0, acc3 = 0;                            \
        _Pragma("unroll")                                                      \
        for (int k = 0; k < D / 2; k++) {                                      \
            ull w0 = regs[2 * k], w1 = regs[2 * k + 1];                        \
            ulonglong2 v0 = p0[k]; ffma2(acc0, w0, v0.x);                      \
            ulonglong2 v1 = p1[k]; ffma2(acc1, w0, v1.x);                      \
            ulonglong2 v2 = p2[k]; ffma2(acc2, w0, v2.x);                      \
            ulonglong2 v3 = p3[k]; ffma2(acc3, w0, v3.x);                      \
            ffma2(acc0, w1, v0.y); ffma2(acc1, w1, v1.y);                      \
            ffma2(acc2, w1, v2.y); ffma2(acc3, w1, v3.y);                      \
        }                                                                      \
        LIF_STEP(acc0, (S));     LIF_STEP(acc1, (S) + 1);                      \
        LIF_STEP(acc2, (S) + 2); LIF_STEP(acc3, (S) + 3);                      \
    }

__global__ __launch_bounds__(128, 2)
void lsnn_kernel(const float* __restrict__ x,
                 const float* __restrict__ enc_w,
                 const float* __restrict__ enc_b,
                 const float* __restrict__ ro_w,
                 const float* __restrict__ ro_b,
                 const float* __restrict__ A,
                 const float* __restrict__ Bv,
                 float* __restrict__ out,     // [BATCH, NCLS] or null
                 float* __restrict__ spk)     // [BATCH, TSTEPS, H]
{
    // 16-slot ring of DUPLICATED state: sd[slot][k] = {s_k, s_k}.
    __shared__ __align__(16) ull sd[RING][D];
    __shared__ float srate[H];

    const int tid = threadIdx.x;
    const int b   = blockIdx.x;
    const float* xb = x + (size_t)b * TSTEPS;

    // Producer = WARP 3 (highest wid).
    const bool is_prod = (tid >= 96);

    // Producer: regs[k] = {A[2j][k], A[2j+1][k]} (scalar chains read halves).
    // Consumer: regs[k] = {enc_w[2c][k], enc_w[2c+1][k]} (FFMA2 dup pairs).
    ull regs[D];
    float Bi0 = 0.f, Bi1 = 0.f;
    float eb0 = 0.f, eb1 = 0.f;
    float mem0 = 0.f, mem1 = 0.f, rate0 = 0.f, rate1 = 0.f;
    float* spkc = nullptr;

    if (is_prod) {
        const int lane = tid - 96;    // owns state elems 2*lane, 2*lane+1
#pragma unroll
        for (int k = 0; k < D; k++)
            regs[k] = pack2(A[(2 * lane) * D + k], A[(2 * lane + 1) * D + k]);
        Bi0 = Bv[2 * lane];
        Bi1 = Bv[2 * lane + 1];
        sd[0][2 * lane]     = 0ull;   // s_0 = 0 in slot 0
        sd[0][2 * lane + 1] = 0ull;
    } else {
        const int c = tid;            // 0..95 -> neurons 2c, 2c+1
#pragma unroll
        for (int k = 0; k < D; k++)
            regs[k] = pack2(enc_w[(2 * c) * D + k], enc_w[(2 * c + 1) * D + k]);
        eb0 = enc_b[2 * c];
        eb1 = enc_b[2 * c + 1];
        spkc = spk + (size_t)b * TSTEPS * H + 2 * c;
    }
    __syncthreads();

    for (int w = 0; w < NWIN; w++) {
        const int t0 = w * KW;
        if (is_prod) {
            // ==== producer: s_{t0+1}..s_{t0+8}; TWO SCALAR fmaf chains ====
            // (scalar FFMA lat=4 vs FFMA2 ~6; A halves = register-pair alias)
            const int lane = tid - 96;
            float uu[KW];
            *reinterpret_cast<float4*>(&uu[0]) =
                *reinterpret_cast<const float4*>(xb + t0);
            *reinterpret_cast<float4*>(&uu[4]) =
                *reinterpret_cast<const float4*>(xb + t0 + 4);
            const int p8 = (w & 1) << 3;
            ull* rb = &sd[p8][0];
#pragma unroll
            for (int i = 0; i < KW; i++) {
                const ulonglong2* sp = (const ulonglong2*)(rb + i * D);
                float acc0 = 0.f, acc1 = 0.f;
#pragma unroll
                for (int k = 0; k < D / 2; k++) {
                    ulonglong2 sv = sp[k];
                    float s0, _d0, s1, _d1;
                    unpack2(sv.x, s0, _d0);          // s_{2k} (dup halves)
                    unpack2(sv.y, s1, _d1);          // s_{2k+1}
                    float a0, a1, b0, b1;
                    unpack2(regs[2 * k],     a0, a1); // A[2j][2k],  A[2j+1][2k]
                    unpack2(regs[2 * k + 1], b0, b1); // A[2j][2k+1],A[2j+1][2k+1]
                    acc0 = __fmaf_rn(a0, s0, acc0);
                    acc1 = __fmaf_rn(a1, s0, acc1);
                    acc0 = __fmaf_rn(b0, s1, acc0);
                    acc1 = __fmaf_rn(b1, s1, acc1);
                }
                const float ns0 = __fmaf_rn(Bi0, uu[i], acc0);  // contracted tail
                const float ns1 = __fmaf_rn(Bi1, uu[i], acc1);
                ulonglong2 st; st.x = pack2(ns0, ns0); st.y = pack2(ns1, ns1);
                ull* wb = (i < KW - 1) ? (rb + (i + 1) * D)
                                       : &sd[(p8 + KW) & (RING - 1)][0];
                ((ulonglong2*)wb)[lane] = st;
                __syncwarp(0xffffffffu);
            }
        } else if (w > 0) {
            // ==== consumers: steps t0-8 .. t0-1 ====
#pragma unroll 1
            for (int pass = 0; pass < 2; pass++) {
                const int S = t0 - KW + 4 * pass;
                CONS_PASS(S);
            }
        }
        __syncthreads();
    }

    // ==== epilogue: consumers process final KW steps ====
    if (!is_prod) {
#pragma unroll 1
        for (int pass = 0; pass < 2; pass++) {
            const int S = TSTEPS - KW + 4 * pass;
            CONS_PASS(S);
        }
        const int c = tid;
        srate[2 * c]     = __fmul_rn(rate0, 1.0f / (float)TSTEPS);
        srate[2 * c + 1] = __fmul_rn(rate1, 1.0f / (float)TSTEPS);
    }
    __syncthreads();

    // ==== readout: sequential-k fmaf chain, separate bias add ====
    if (tid < NCLS && out != nullptr) {
        float acc = 0.f;
        const float* rw = ro_w + tid * H;
#pragma unroll
        for (int h = 0; h < H; h++)
            acc = __fmaf_rn(rw[h], srate[h], acc);
        out[b * NCLS + tid] = __fadd_rn(acc, ro_b[tid]);
    }
}

extern "C" void kernel_launch(void* const* d_in, const int* in_sizes, int n_in,
                              void* d_out, int out_size) {
    const float* x     = (const float*)d_in[0];
    const float* enc_w = (const float*)d_in[1];
    const float* enc_b = (const float*)d_in[2];
    const float* ro_w  = (const float*)d_in[3];
    const float* ro_b  = (const float*)d_in[4];
    const float* A     = (const float*)d_in[5];
    const float* Bv    = (const float*)d_in[6];

    float* base = (float*)d_out;
    const long long spkElems = (long long)BATCH * TSTEPS * H;   // 201326592
    const long long outElems = (long long)BATCH * NCLS;          // 2560

    float* outp;
    float* spkp;
    if ((long long)out_size >= spkElems + outElems) {
        outp = base;
        spkp = base + outElems;
    } else {
        outp = nullptr;
        spkp = base;
    }

    lsnn_kernel<<<BATCH, 128>>>(x, enc_w, enc_b, ro_w, ro_b, A, Bv, outp, spkp);
}

// round 16
// speedup vs baseline: 1.0389x; 1.0389x over previous
#include <cuda_runtime.h>

#define BATCH 256
#define TSTEPS 4096
#define D 64
#define H 192
#define NCLS 10
#define BETA 0.9f
#define KW 8
#define RING 16
#define NWIN (TSTEPS / KW)

typedef unsigned long long ull;

__device__ __forceinline__ ull pack2(float x, float y) {
    ull v; asm("mov.b64 %0, {%1, %2};" : "=l"(v) : "f"(x), "f"(y)); return v;
}
__device__ __forceinline__ void unpack2(ull v, float& x, float& y) {
    asm("mov.b64 {%0, %1}, %2;" : "=f"(x), "=f"(y) : "l"(v));
}
__device__ __forceinline__ void ffma2(ull& d, ull a, ull b) {
    asm("fma.rn.f32x2 %0, %1, %2, %0;" : "+l"(d) : "l"(a), "l"(b));
}

// LIF update for 2 neurons; op order identical to the proven-exact R4/R5 form.
// Internal locals use reserved _l* names (R6 shadowing bug guard).
#define LIF_STEP(ACC, TIDX)                                                    \
    {                                                                          \
        float _la, _lb; unpack2((ACC), _la, _lb);                              \
        float _cur0 = __fadd_rn(_la, eb0);                                     \
        float _cur1 = __fadd_rn(_lb, eb1);                                     \
        mem0 = __fmaf_rn(BETA, mem0, _cur0);                                   \
        mem1 = __fmaf_rn(BETA, mem1, _cur1);                                   \
        float _s0 = (__fadd_rn(mem0, -1.0f) > 0.f) ? 1.f : 0.f;                \
        float _s1 = (__fadd_rn(mem1, -1.0f) > 0.f) ? 1.f : 0.f;                \
        rate0 = __fadd_rn(rate0, _s0);                                         \
        rate1 = __fadd_rn(rate1, _s1);                                         \
        *reinterpret_cast<float2*>(spkc + (size_t)(TIDX) * H) =                \
            make_float2(_s0, _s1);                                             \
        mem0 = __fmul_rn(mem0, __fadd_rn(1.0f, -_s0));                         \
        mem1 = __fmul_rn(mem1, __fadd_rn(1.0f, -_s1));                         \
    }

// Consumer pass: 4 consecutive LIF steps S..S+3 (states s_{S+1}..s_{S+4}).
// 4 independent sequential-k chains interleaved; per-chain k-order preserved.
#define CONS_PASS(S)                                                           \
    {                                                                          \
        const ulonglong2* p0 = (const ulonglong2*)sd[((S) + 1) & (RING - 1)];  \
        const ulonglong2* p1 = (const ulonglong2*)sd[((S) + 2) & (RING - 1)];  \
        const ulonglong2* p2 = (const ulonglong2*)sd[((S) + 3) & (RING - 1)];  \
        const ulonglong2* p3 = (const ulonglong2*)sd[((S) + 4) & (RING - 1)];  \
        ull acc0 = 0, acc1 = 0, acc2 = 0, acc3 = 0;                            \
        _Pragma("unroll")                                                      \
        for (int k = 0; k < D / 2; k++) {                                      \
            ull w0 = regs[2 * k], w1 = regs[2 * k + 1];                        \
            ulonglong2 v0 = p0[k]; ffma2(acc0, w0, v0.x);                      \
            ulonglong2 v1 = p1[k]; ffma2(acc1, w0, v1.x);                      \
            ulonglong2 v2 = p2[k]; ffma2(acc2, w0, v2.x);                      \
            ulonglong2 v3 = p3[k]; ffma2(acc3, w0, v3.x);                      \
            ffma2(acc0, w1, v0.y); ffma2(acc1, w1, v1.y);                      \
            ffma2(acc2, w1, v2.y); ffma2(acc3, w1, v3.y);                      \
        }                                                                      \
        LIF_STEP(acc0, (S));     LIF_STEP(acc1, (S) + 1);                      \
        LIF_STEP(acc2, (S) + 2); LIF_STEP(acc3, (S) + 3);                      \
    }

__global__ __launch_bounds__(128, 2)
void lsnn_kernel(const float* __restrict__ x,
                 const float* __restrict__ enc_w,
                 const float* __restrict__ enc_b,
                 const float* __restrict__ ro_w,
                 const float* __restrict__ ro_b,
                 const float* __restrict__ A,
                 const float* __restrict__ Bv,
                 float* __restrict__ out,     // [BATCH, NCLS] or null
                 float* __restrict__ spk)     // [BATCH, TSTEPS, H]
{
    // 16-slot ring of DUPLICATED state: sd[slot][k] = {s_k, s_k}.
    __shared__ __align__(16) ull sd[RING][D];
    __shared__ float srate[H];

    const int tid  = threadIdx.x;
    const int wid  = tid >> 5;
    const int lane = tid & 31;
    const int b    = blockIdx.x;
    const float* xb = x + (size_t)b * TSTEPS;

    // Producer warp alternates with block parity: even blocks -> warp 3,
    // odd blocks -> warp 2.  Co-resident blocks (consecutive IDs) thus put
    // their latency-critical producer chains on DIFFERENT SMSPs.
    const int  PW      = 3 - (b & 1);
    const bool is_prod = (wid == PW);
    // Consumer rank 0..2 among the three non-producer warps.
    const int  crank   = wid - (wid > PW ? 1 : 0);

    ull regs[D];                      // A rows (producer) or enc_w rows (consumer)
    ull B2 = 0;
    float eb0 = 0.f, eb1 = 0.f;
    float mem0 = 0.f, mem1 = 0.f, rate0 = 0.f, rate1 = 0.f;
    float* spkc = nullptr;

    if (is_prod) {
        // producer: lane owns state elems 2*lane, 2*lane+1
#pragma unroll
        for (int k = 0; k < D; k++)
            regs[k] = pack2(A[(2 * lane) * D + k], A[(2 * lane + 1) * D + k]);
        B2 = pack2(Bv[2 * lane], Bv[2 * lane + 1]);
        sd[0][2 * lane]     = 0ull;   // s_0 = 0 in slot 0
        sd[0][2 * lane + 1] = 0ull;
    } else {
        const int c = crank * 32 + lane;   // 0..95 -> neurons 2c, 2c+1
#pragma unroll
        for (int k = 0; k < D; k++)
            regs[k] = pack2(enc_w[(2 * c) * D + k], enc_w[(2 * c + 1) * D + k]);
        eb0 = enc_b[2 * c];
        eb1 = enc_b[2 * c + 1];
        spkc = spk + (size_t)b * TSTEPS * H + 2 * c;
    }
    __syncthreads();

    for (int w = 0; w < NWIN; w++) {
        const int t0 = w * KW;
        if (is_prod) {
            // ==== producer: s_{t0+1} .. s_{t0+8}, FULLY UNROLLED window ====
            float uu[KW];
            *reinterpret_cast<float4*>(&uu[0]) =
                *reinterpret_cast<const float4*>(xb + t0);
            *reinterpret_cast<float4*>(&uu[4]) =
                *reinterpret_cast<const float4*>(xb + t0 + 4);
            // Window w reads slots p8+0..p8+7, writes p8+1..p8+8 (mod 16).
            const int p8 = (w & 1) << 3;
            ull* rb = &sd[p8][0];
#pragma unroll
            for (int i = 0; i < KW; i++) {
                const ulonglong2* sp = (const ulonglong2*)(rb + i * D);
                ull acc = 0ull;
#pragma unroll
                for (int k = 0; k < D / 2; k++) {
                    ulonglong2 sv = sp[k];
                    ffma2(acc, regs[2 * k],     sv.x);
                    ffma2(acc, regs[2 * k + 1], sv.y);
                }
                ffma2(acc, B2, pack2(uu[i], uu[i]));  // + B*u (contracted fma)
                float lo, hi; unpack2(acc, lo, hi);
                ulonglong2 st; st.x = pack2(lo, lo); st.y = pack2(hi, hi);
                ull* wb = (i < KW - 1) ? (rb + (i + 1) * D)
                                       : &sd[(p8 + KW) & (RING - 1)][0];
                ((ulonglong2*)wb)[lane] = st;
                // last step's visibility is provided by __syncthreads below
                if (i < KW - 1) __syncwarp(0xffffffffu);
            }
        } else if (w > 0) {
            // ==== consumers: steps t0-8 .. t0-1 ====
#pragma unroll 1
            for (int pass = 0; pass < 2; pass++) {
                const int S = t0 - KW + 4 * pass;
                CONS_PASS(S);
            }
        }
        __syncthreads();
    }

    // ==== epilogue: consumers process final KW steps ====
    if (!is_prod) {
#pragma unroll 1
        for (int pass = 0; pass < 2; pass++) {
            const int S = TSTEPS - KW + 4 * pass;
            CONS_PASS(S);
        }
        const int c = crank * 32 + lane;
        srate[2 * c]     = __fmul_rn(rate0, 1.0f / (float)TSTEPS);
        srate[2 * c + 1] = __fmul_rn(rate1, 1.0f / (float)TSTEPS);
    }
    __syncthreads();

    // ==== readout: sequential-k fmaf chain, separate bias add ====
    if (tid < NCLS && out != nullptr) {
        float acc = 0.f;
        const float* rw = ro_w + tid * H;
#pragma unroll
        for (int h = 0; h < H; h++)
            acc = __fmaf_rn(rw[h], srate[h], acc);
        out[b * NCLS + tid] = __fadd_rn(acc, ro_b[tid]);
    }
}

extern "C" void kernel_launch(void* const* d_in, const int* in_sizes, int n_in,
                              void* d_out, int out_size) {
    const float* x     = (const float*)d_in[0];
    const float* enc_w = (const float*)d_in[1];
    const float* enc_b = (const float*)d_in[2];
    const float* ro_w  = (const float*)d_in[3];
    const float* ro_b  = (const float*)d_in[4];
    const float* A     = (const float*)d_in[5];
    const float* Bv    = (const float*)d_in[6];

    float* base = (float*)d_out;
    const long long spkElems = (long long)BATCH * TSTEPS * H;   // 201326592
    const long long outElems = (long long)BATCH * NCLS;          // 2560

    float* outp;
    float* spkp;
    if ((long long)out_size >= spkElems + outElems) {
        outp = base;
        spkp = base + outElems;
    } else {
        outp = nullptr;
        spkp = base;
    }

    lsnn_kernel<<<BATCH, 128>>>(x, enc_w, enc_b, ro_w, ro_b, A, Bv, outp, spkp);
}

// round 17
// speedup vs baseline: 1.2318x; 1.1857x over previous
#include <cuda_runtime.h>

#define BATCH 256
#define TSTEPS 4096
#define D 64
#define H 192
#define NCLS 10
#define BETA 0.9f
#define KW 8
#define RING 16
#define NWIN (TSTEPS / KW)

typedef unsigned long long ull;

__device__ __forceinline__ ull pack2(float x, float y) {
    ull v; asm("mov.b64 %0, {%1, %2};" : "=l"(v) : "f"(x), "f"(y)); return v;
}
__device__ __forceinline__ void unpack2(ull v, float& x, float& y) {
    asm("mov.b64 {%0, %1}, %2;" : "=f"(x), "=f"(y) : "l"(v));
}
__device__ __forceinline__ void ffma2(ull& d, ull a, ull b) {
    asm("fma.rn.f32x2 %0, %1, %2, %0;" : "+l"(d) : "l"(a), "l"(b));
}

// LIF update for 2 neurons; op order identical to the proven-exact R4/R5 form.
// Internal locals use reserved _l* names (R6 shadowing bug guard).
#define LIF_STEP(ACC, TIDX)                                                    \
    {                                                                          \
        float _la, _lb; unpack2((ACC), _la, _lb);                              \
        float _cur0 = __fadd_rn(_la, eb0);                                     \
        float _cur1 = __fadd_rn(_lb, eb1);                                     \
        mem0 = __fmaf_rn(BETA, mem0, _cur0);                                   \
        mem1 = __fmaf_rn(BETA, mem1, _cur1);                                   \
        float _s0 = (__fadd_rn(mem0, -1.0f) > 0.f) ? 1.f : 0.f;                \
        float _s1 = (__fadd_rn(mem1, -1.0f) > 0.f) ? 1.f : 0.f;                \
        rate0 = __fadd_rn(rate0, _s0);                                         \
        rate1 = __fadd_rn(rate1, _s1);                                         \
        *reinterpret_cast<float2*>(spkc + (size_t)(TIDX) * H) =                \
            make_float2(_s0, _s1);                                             \
        mem0 = __fmul_rn(mem0, __fadd_rn(1.0f, -_s0));                         \
        mem1 = __fmul_rn(mem1, __fadd_rn(1.0f, -_s1));                         \
    }

// Consumer pass over 4 steps S..S+3 (states s_{S+1}..s_{S+4}) reading the
// PLAIN ring (float4 = 4 k-values per load, HALF the LDS instructions of the
// old dup-format). Dup operands rebuilt via register MOVs (free issue slack).
// 4 independent sequential-k FFMA2 chains; per-chain k-order 0..63 preserved.
#define CONS_PASS(S)                                                           \
    {                                                                          \
        const float4* q0 = (const float4*)spr[((S) + 1) & (RING - 1)];         \
        const float4* q1 = (const float4*)spr[((S) + 2) & (RING - 1)];         \
        const float4* q2 = (const float4*)spr[((S) + 3) & (RING - 1)];         \
        const float4* q3 = (const float4*)spr[((S) + 4) & (RING - 1)];         \
        ull acc0 = 0, acc1 = 0, acc2 = 0, acc3 = 0;                            \
        _Pragma("unroll")                                                      \
        for (int q = 0; q < D / 4; q++) {                                      \
            float4 v0 = q0[q]; float4 v1 = q1[q];                              \
            float4 v2 = q2[q]; float4 v3 = q3[q];                              \
            ffma2(acc0, regs[4 * q + 0], pack2(v0.x, v0.x));                   \
            ffma2(acc1, regs[4 * q + 0], pack2(v1.x, v1.x));                   \
            ffma2(acc2, regs[4 * q + 0], pack2(v2.x, v2.x));                   \
            ffma2(acc3, regs[4 * q + 0], pack2(v3.x, v3.x));                   \
            ffma2(acc0, regs[4 * q + 1], pack2(v0.y, v0.y));                   \
            ffma2(acc1, regs[4 * q + 1], pack2(v1.y, v1.y));                   \
            ffma2(acc2, regs[4 * q + 1], pack2(v2.y, v2.y));                   \
            ffma2(acc3, regs[4 * q + 1], pack2(v3.y, v3.y));                   \
            ffma2(acc0, regs[4 * q + 2], pack2(v0.z, v0.z));                   \
            ffma2(acc1, regs[4 * q + 2], pack2(v1.z, v1.z));                   \
            ffma2(acc2, regs[4 * q + 2], pack2(v2.z, v2.z));                   \
            ffma2(acc3, regs[4 * q + 2], pack2(v3.z, v3.z));                   \
            ffma2(acc0, regs[4 * q + 3], pack2(v0.w, v0.w));                   \
            ffma2(acc1, regs[4 * q + 3], pack2(v1.w, v1.w));                   \
            ffma2(acc2, regs[4 * q + 3], pack2(v2.w, v2.w));                   \
            ffma2(acc3, regs[4 * q + 3], pack2(v3.w, v3.w));                   \
        }                                                                      \
        LIF_STEP(acc0, (S));     LIF_STEP(acc1, (S) + 1);                      \
        LIF_STEP(acc2, (S) + 2); LIF_STEP(acc3, (S) + 3);                      \
    }

__global__ __launch_bounds__(128, 2)
void lsnn_kernel(const float* __restrict__ x,
                 const float* __restrict__ enc_w,
                 const float* __restrict__ enc_b,
                 const float* __restrict__ ro_w,
                 const float* __restrict__ ro_b,
                 const float* __restrict__ A,
                 const float* __restrict__ Bv,
                 float* __restrict__ out,     // [BATCH, NCLS] or null
                 float* __restrict__ spk)     // [BATCH, TSTEPS, H]
{
    // 16-slot PLAIN ring: spr[slot][k] = s_k (4 KB; halves LDS wavefronts).
    __shared__ __align__(16) float spr[RING][D];
    __shared__ float srate[H];

    const int tid  = threadIdx.x;
    const int wid  = tid >> 5;
    const int lane = tid & 31;
    const int b    = blockIdx.x;
    const float* xb = x + (size_t)b * TSTEPS;

    // Producer warp alternates with block parity (R16: co-resident blocks'
    // producers land on different SMSPs).
    const int  PW      = 3 - (b & 1);
    const bool is_prod = (wid == PW);
    const int  crank   = wid - (wid > PW ? 1 : 0);

    ull regs[D];                      // A rows (producer) or enc_w rows (consumer)
    ull B2 = 0;
    float eb0 = 0.f, eb1 = 0.f;
    float mem0 = 0.f, mem1 = 0.f, rate0 = 0.f, rate1 = 0.f;
    float* spkc = nullptr;

    if (is_prod) {
        // producer: lane owns state elems 2*lane, 2*lane+1
#pragma unroll
        for (int k = 0; k < D; k++)
            regs[k] = pack2(A[(2 * lane) * D + k], A[(2 * lane + 1) * D + k]);
        B2 = pack2(Bv[2 * lane], Bv[2 * lane + 1]);
        ((float2*)spr[0])[lane] = make_float2(0.f, 0.f);   // s_0 = 0
    } else {
        const int c = crank * 32 + lane;   // 0..95 -> neurons 2c, 2c+1
#pragma unroll
        for (int k = 0; k < D; k++)
            regs[k] = pack2(enc_w[(2 * c) * D + k], enc_w[(2 * c + 1) * D + k]);
        eb0 = enc_b[2 * c];
        eb1 = enc_b[2 * c + 1];
        spkc = spk + (size_t)b * TSTEPS * H + 2 * c;
    }
    __syncthreads();

    for (int w = 0; w < NWIN; w++) {
        const int t0 = w * KW;
        if (is_prod) {
            // ==== producer: s_{t0+1}..s_{t0+8}, fully unrolled window ====
            float uu[KW];
            *reinterpret_cast<float4*>(&uu[0]) =
                *reinterpret_cast<const float4*>(xb + t0);
            *reinterpret_cast<float4*>(&uu[4]) =
                *reinterpret_cast<const float4*>(xb + t0 + 4);
            const int p8 = (w & 1) << 3;
            float* rb = &spr[p8][0];
#pragma unroll
            for (int i = 0; i < KW; i++) {
                const float4* sp = (const float4*)(rb + i * D);
                ull acc = 0ull;
#pragma unroll
                for (int q = 0; q < D / 4; q++) {
                    float4 v = sp[q];
                    ffma2(acc, regs[4 * q + 0], pack2(v.x, v.x));
                    ffma2(acc, regs[4 * q + 1], pack2(v.y, v.y));
                    ffma2(acc, regs[4 * q + 2], pack2(v.z, v.z));
                    ffma2(acc, regs[4 * q + 3], pack2(v.w, v.w));
                }
                ffma2(acc, B2, pack2(uu[i], uu[i]));  // + B*u (contracted fma)
                float lo, hi; unpack2(acc, lo, hi);
                float* wb = (i < KW - 1) ? (rb + (i + 1) * D)
                                         : &spr[(p8 + KW) & (RING - 1)][0];
                ((float2*)wb)[lane] = make_float2(lo, hi);
                if (i < KW - 1) __syncwarp(0xffffffffu);
            }
        } else if (w > 0) {
            // ==== consumers: steps t0-8 .. t0-1 ====
#pragma unroll 1
            for (int pass = 0; pass < 2; pass++) {
                const int S = t0 - KW + 4 * pass;
                CONS_PASS(S);
            }
        }
        __syncthreads();
    }

    // ==== epilogue: consumers process final KW steps ====
    if (!is_prod) {
#pragma unroll 1
        for (int pass = 0; pass < 2; pass++) {
            const int S = TSTEPS - KW + 4 * pass;
            CONS_PASS(S);
        }
        const int c = crank * 32 + lane;
        srate[2 * c]     = __fmul_rn(rate0, 1.0f / (float)TSTEPS);
        srate[2 * c + 1] = __fmul_rn(rate1, 1.0f / (float)TSTEPS);
    }
    __syncthreads();

    // ==== readout: sequential-k fmaf chain, separate bias add ====
    if (tid < NCLS && out != nullptr) {
        float acc = 0.f;
        const float* rw = ro_w + tid * H;
#pragma unroll
        for (int h = 0; h < H; h++)
            acc = __fmaf_rn(rw[h], srate[h], acc);
        out[b * NCLS + tid] = __fadd_rn(acc, ro_b[tid]);
    }
}

extern "C" void kernel_launch(void* const* d_in, const int* in_sizes, int n_in,
                              void* d_out, int out_size) {
    const float* x     = (const float*)d_in[0];
    const float* enc_w = (const float*)d_in[1];
    const float* enc_b = (const float*)d_in[2];
    const float* ro_w  = (const float*)d_in[3];
    const float* ro_b  = (const float*)d_in[4];
    const float* A     = (const float*)d_in[5];
    const float* Bv    = (const float*)d_in[6];

    float* base = (float*)d_out;
    const long long spkElems = (long long)BATCH * TSTEPS * H;   // 201326592
    const long long outElems = (long long)BATCH * NCLS;          // 2560

    float* outp;
    float* spkp;
    if ((long long)out_size >= spkElems + outElems) {
        outp = base;
        spkp = base + outElems;
    } else {
        outp = nullptr;
        spkp = base;
    }

    lsnn_kernel<<<BATCH, 128>>>(x, enc_w, enc_b, ro_w, ro_b, A, Bv, outp, spkp);
}